// round 1
// baseline (speedup 1.0000x reference)
#include <cuda_runtime.h>
#include <cstdint>

#define B  16
#define C  96
#define HH 224
#define WWW 224
#define HW (HH*WWW)      // 50176
#define HW4 (HW/4)       // 12544
#define KSEL (HW/2)      // 25088

// Scratch (no allocs allowed): energy^2 per position, per-batch threshold key,
// packed 1-bit mask per position.
__device__ float        g_e2[B*HW];            // 3.2 MB
__device__ unsigned int g_thresh[B];
__device__ unsigned int g_maskbits[B*HW/32];   // 100 KB

// ---------------------------------------------------------------------------
// Pass 1: energy2[b][hw] = sum_c x[b][c][hw]^2.  float4 over hw; c-loop strided.
// ---------------------------------------------------------------------------
__global__ void energy_kernel(const float4* __restrict__ x) {
    int idx = blockIdx.x * blockDim.x + threadIdx.x;   // over B*HW4
    if (idx >= B*HW4) return;
    int b = idx / HW4;
    int p = idx - b * HW4;
    const float4* base = x + (size_t)b * (C * HW4) + p;
    float ax = 0.f, ay = 0.f, az = 0.f, aw = 0.f;
#pragma unroll 8
    for (int c = 0; c < C; c++) {
        float4 v = __ldg(base + (size_t)c * HW4);
        ax += v.x * v.x;
        ay += v.y * v.y;
        az += v.z * v.z;
        aw += v.w * v.w;
    }
    float4 r; r.x = ax; r.y = ay; r.z = az; r.w = aw;
    reinterpret_cast<float4*>(g_e2)[idx] = r;
}

// ---------------------------------------------------------------------------
// Pass 2: per-batch exact k-th-largest via MSB-first 8-bit radix select.
// energy2 >= 0, so its uint32 bit pattern is order-isomorphic to the float.
// One block per batch; warp-aggregated shared-mem histogram (exponent digits
// are nearly constant -> raw same-address atomics would serialize badly).
// HW = 49 * 1024 exactly, so the scan loop is fully converged for match_any.
// ---------------------------------------------------------------------------
__global__ void select_kernel() {
    int b = blockIdx.x;
    const unsigned int* keys = reinterpret_cast<const unsigned int*>(g_e2) + b * HW;
    __shared__ unsigned int hist[256];
    __shared__ unsigned int s_prefix;
    __shared__ int          s_remk;

    unsigned int prefix = 0;
    int remk = KSEL;

    for (int pass = 0; pass < 4; pass++) {
        int shift = 24 - 8 * pass;
        for (int i = threadIdx.x; i < 256; i += blockDim.x) hist[i] = 0;
        __syncthreads();

        unsigned int pmask = (pass == 0) ? 0u : (0xFFFFFFFFu << (shift + 8));
        for (int i = threadIdx.x; i < HW; i += blockDim.x) {
            unsigned int key = keys[i];
            unsigned int dig = 0xFFFFFFFFu;  // sentinel: not in current prefix group
            if ((key & pmask) == prefix) dig = (key >> shift) & 255u;
            unsigned int m = __match_any_sync(0xFFFFFFFFu, dig);
            int leader = __ffs(m) - 1;
            if (dig != 0xFFFFFFFFu && (int)(threadIdx.x & 31) == leader)
                atomicAdd(&hist[dig], (unsigned)__popc(m));
        }
        __syncthreads();

        if (threadIdx.x == 0) {
            // Invariant: sum(hist) >= remk, so the walk always terminates.
            int cum = 0;
            int bin = 255;
            for (;; bin--) {
                cum += (int)hist[bin];
                if (cum >= remk) break;
            }
            remk  -= (cum - (int)hist[bin]);   // rank within the chosen bin
            prefix |= ((unsigned)bin) << shift;
            s_prefix = prefix;
            s_remk   = remk;
        }
        __syncthreads();
        prefix = s_prefix;
        remk   = s_remk;
    }
    if (threadIdx.x == 0) g_thresh[b] = prefix;  // exact key of k-th largest
}

// ---------------------------------------------------------------------------
// Pass 3: pack (energy2 >= thresh) into bits via ballot. 1 warp = 32 positions.
// ---------------------------------------------------------------------------
__global__ void maskbuild_kernel() {
    int idx = blockIdx.x * blockDim.x + threadIdx.x;   // over B*HW (divides 256)
    int b = idx / HW;                                  // warps never straddle b (HW % 32 == 0)
    unsigned int key = reinterpret_cast<const unsigned int*>(g_e2)[idx];
    unsigned int t   = g_thresh[b];
    unsigned int bal = __ballot_sync(0xFFFFFFFFu, key >= t);
    if ((threadIdx.x & 31) == 0) g_maskbits[idx >> 5] = bal;
}

// ---------------------------------------------------------------------------
// Pass 4: out = x * mask. float4 per thread; 4 bits from the packed mask
// (100 KB, L1/L2-resident broadcast loads).
// ---------------------------------------------------------------------------
__global__ void mask_kernel(const float4* __restrict__ x, float4* __restrict__ out) {
    int idx = blockIdx.x * blockDim.x + threadIdx.x;   // over B*C*HW4
    if (idx >= B * C * HW4) return;
    int b  = idx / (C * HW4);
    int p  = idx % HW4;
    int hw = p * 4;
    unsigned int bits = g_maskbits[((unsigned)(b * HW + hw)) >> 5] >> (hw & 31);
    float4 v = x[(size_t)idx];
    float4 r;
    r.x = (bits & 1u) ? v.x : 0.f;
    r.y = (bits & 2u) ? v.y : 0.f;
    r.z = (bits & 4u) ? v.z : 0.f;
    r.w = (bits & 8u) ? v.w : 0.f;
    out[(size_t)idx] = r;
}

extern "C" void kernel_launch(void* const* d_in, const int* in_sizes, int n_in,
                              void* d_out, int out_size) {
    const float* x = (const float*)d_in[0];
    float*     out = (float*)d_out;

    energy_kernel<<<(B * HW4 + 255) / 256, 256>>>((const float4*)x);
    select_kernel<<<B, 1024>>>();
    maskbuild_kernel<<<(B * HW) / 256, 256>>>();
    mask_kernel<<<(B * C * HW4 + 255) / 256, 256>>>((const float4*)x, (float4*)out);
}

// round 2
// speedup vs baseline: 1.2390x; 1.2390x over previous
#include <cuda_runtime.h>
#include <cstdint>

#define B    16
#define C    96
#define HW   50176
#define HW4  12544
#define KSEL 25088
#define CHUNKS 3
#define CPT  32      // channels per chunk
#define NB   2048    // radix bins (11 bits)

// Scratch: per-chunk partial energy^2, combined energy^2, packed mask bits.
__device__ float        g_part[CHUNKS * B * HW];   // 9.6 MB
__device__ float        g_e2[B * HW];              // 3.2 MB
__device__ unsigned int g_maskbits[B * HW / 32];   // 100 KB

// ---------------------------------------------------------------------------
// Pass 1: partial energy over 32-channel chunks. 602K threads = 2 full waves.
// ---------------------------------------------------------------------------
__global__ void energy_kernel(const float4* __restrict__ x) {
    int idx = blockIdx.x * blockDim.x + threadIdx.x;      // over CHUNKS*B*HW4
    if (idx >= CHUNKS * B * HW4) return;
    int chunk = idx / (B * HW4);
    int r     = idx - chunk * (B * HW4);
    int b     = r / HW4;
    int p     = r - b * HW4;
    const float4* base = x + (size_t)b * (C * HW4) + (size_t)(chunk * CPT) * HW4 + p;
    float ax = 0.f, ay = 0.f, az = 0.f, aw = 0.f;
#pragma unroll 16
    for (int c = 0; c < CPT; c++) {
        float4 v = __ldg(base + (size_t)c * HW4);
        ax += v.x * v.x; ay += v.y * v.y; az += v.z * v.z; aw += v.w * v.w;
    }
    float4 o; o.x = ax; o.y = ay; o.z = az; o.w = aw;
    reinterpret_cast<float4*>(g_part)[idx] = o;
}

// ---------------------------------------------------------------------------
// Pass 2: combine the 3 partials (all L2-resident). Deterministic add order.
// ---------------------------------------------------------------------------
__global__ void combine_kernel() {
    int idx = blockIdx.x * blockDim.x + threadIdx.x;      // over B*HW4
    const float4* p = reinterpret_cast<const float4*>(g_part);
    float4 a = p[idx];
    float4 b4 = p[idx + B * HW4];
    float4 c4 = p[idx + 2 * B * HW4];
    float4 o;
    o.x = a.x + b4.x + c4.x;
    o.y = a.y + b4.y + c4.y;
    o.z = a.z + b4.z + c4.z;
    o.w = a.w + b4.w + c4.w;
    reinterpret_cast<float4*>(g_e2)[idx] = o;
}

// ---------------------------------------------------------------------------
// Pass 3: exact k-th-largest per batch via 3-pass MSB radix select
// (11/11/10 bits), parallel suffix-scan bin pick, fused maskbit build.
// energy2 >= 0 so uint bit order == float order.
// ---------------------------------------------------------------------------
__global__ void select_kernel() {
    int b   = blockIdx.x;
    int tid = threadIdx.x;
    const unsigned int* keys  = reinterpret_cast<const unsigned int*>(g_e2) + b * HW;
    const uint4*        keys4 = reinterpret_cast<const uint4*>(keys);

    __shared__ unsigned int hist[NB];
    __shared__ unsigned int ss[1024];
    __shared__ unsigned int s_prefix;
    __shared__ unsigned int s_remk;

    unsigned int prefix = 0;
    unsigned int remk   = KSEL;

#pragma unroll
    for (int pass = 0; pass < 3; pass++) {
        const int shift = (pass == 0) ? 21 : (pass == 1) ? 10 : 0;
        const unsigned int pmask =
            (pass == 0) ? 0u : (pass == 1) ? 0xFFE00000u : 0xFFFFFC00u;

        for (int i = tid; i < NB; i += 1024) hist[i] = 0;
        __syncthreads();

        // Histogram with warp-aggregated shared atomics (digits cluster hard).
        for (int i = tid; i < HW4; i += 1024) {
            uint4 kv = keys4[i];
#pragma unroll
            for (int j = 0; j < 4; j++) {
                unsigned int key = (j == 0) ? kv.x : (j == 1) ? kv.y : (j == 2) ? kv.z : kv.w;
                unsigned int dig = ((key & pmask) == prefix)
                                       ? ((key >> shift) & 2047u)
                                       : 0xFFFFFFFFu;
                unsigned int m = __match_any_sync(0xFFFFFFFFu, dig);
                if (dig != 0xFFFFFFFFu && (int)(tid & 31) == (__ffs(m) - 1))
                    atomicAdd(&hist[dig], (unsigned)__popc(m));
            }
        }
        __syncthreads();

        // Parallel suffix sums over 1024 two-bin segments (Hillis-Steele).
        unsigned int h0 = hist[2 * tid], h1 = hist[2 * tid + 1];
        ss[tid] = h0 + h1;
        __syncthreads();
        for (int off = 1; off < 1024; off <<= 1) {
            unsigned int v = (tid + off < 1024) ? ss[tid + off] : 0u;
            __syncthreads();
            ss[tid] += v;
            __syncthreads();
        }
        unsigned int ss_next = (tid + 1 < 1024) ? ss[tid + 1] : 0u;
        // S(2t+1) = ss_next + h1 ; S(2t) = S(2t+1) + h0 ; S(2t+2) = ss_next.
        unsigned int S1 = ss_next + h1;
        unsigned int S0 = S1 + h0;
        unsigned int S2 = ss_next;
        // Exactly one bin satisfies S(bin) >= remk && S(bin+1) < remk.
        if (S1 >= remk && S2 < remk) {
            s_prefix = prefix | ((2u * tid + 1u) << shift);
            s_remk   = remk - S2;
        }
        if (S0 >= remk && S1 < remk) {
            s_prefix = prefix | ((2u * tid) << shift);
            s_remk   = remk - S1;
        }
        __syncthreads();
        prefix = s_prefix;
        remk   = s_remk;
        __syncthreads();   // protect hist reuse next pass
    }

    // Fused maskbuild: ballot-pack (key >= thresh). 49 exact iterations.
    unsigned int t = prefix;
    for (int i = tid; i < HW; i += 1024) {
        unsigned int key = keys[i];
        unsigned int bal = __ballot_sync(0xFFFFFFFFu, key >= t);
        if ((tid & 31) == 0) g_maskbits[(b * HW + i) >> 5] = bal;
    }
}

// ---------------------------------------------------------------------------
// Pass 4: out = x * mask (float4, bitmask broadcast from L1/L2). At roofline.
// ---------------------------------------------------------------------------
__global__ void mask_kernel(const float4* __restrict__ x, float4* __restrict__ out) {
    int idx = blockIdx.x * blockDim.x + threadIdx.x;      // over B*C*HW4
    if (idx >= B * C * HW4) return;
    int b  = idx / (C * HW4);
    int p  = idx % HW4;
    int hw = p * 4;
    unsigned int bits = g_maskbits[((unsigned)(b * HW + hw)) >> 5] >> (hw & 31);
    float4 v = x[(size_t)idx];
    float4 r;
    r.x = (bits & 1u) ? v.x : 0.f;
    r.y = (bits & 2u) ? v.y : 0.f;
    r.z = (bits & 4u) ? v.z : 0.f;
    r.w = (bits & 8u) ? v.w : 0.f;
    out[(size_t)idx] = r;
}

extern "C" void kernel_launch(void* const* d_in, const int* in_sizes, int n_in,
                              void* d_out, int out_size) {
    const float* x = (const float*)d_in[0];
    float*     out = (float*)d_out;

    energy_kernel<<<(CHUNKS * B * HW4) / 256, 256>>>((const float4*)x);
    combine_kernel<<<(B * HW4) / 256, 256>>>();
    select_kernel<<<B, 1024>>>();
    mask_kernel<<<(B * C * HW4 + 255) / 256, 256>>>((const float4*)x, (float4*)out);
}

// round 3
// speedup vs baseline: 1.2520x; 1.0105x over previous
#include <cuda_runtime.h>
#include <cstdint>

#define B    16
#define C    96
#define HW   50176
#define HW4  12544
#define KSEL 25088
#define CHUNKS 3
#define CPT  32      // channels per chunk
#define NB   2048    // radix bins (11 bits)

// Scratch: per-chunk partial energy^2, combined energy^2, packed mask bits.
__device__ float        g_part[CHUNKS * B * HW];   // 9.6 MB (L2-resident)
__device__ float        g_e2[B * HW];              // 3.2 MB (L2-resident)
__device__ unsigned int g_maskbits[B * HW / 32];   // 100 KB

// ---------------------------------------------------------------------------
// Pass 1: partial energy over 32-channel chunks. 602K threads ~= 2 full waves.
// x is streamed (touched once here) -> evict-first loads.
// ---------------------------------------------------------------------------
__global__ void energy_kernel(const float4* __restrict__ x) {
    int idx = blockIdx.x * blockDim.x + threadIdx.x;      // over CHUNKS*B*HW4
    if (idx >= CHUNKS * B * HW4) return;
    int chunk = idx / (B * HW4);
    int r     = idx - chunk * (B * HW4);
    int b     = r / HW4;
    int p     = r - b * HW4;
    const float4* base = x + (size_t)b * (C * HW4) + (size_t)(chunk * CPT) * HW4 + p;
    float ax = 0.f, ay = 0.f, az = 0.f, aw = 0.f;
#pragma unroll 16
    for (int c = 0; c < CPT; c++) {
        float4 v = __ldcs(base + (size_t)c * HW4);
        ax += v.x * v.x; ay += v.y * v.y; az += v.z * v.z; aw += v.w * v.w;
    }
    float4 o; o.x = ax; o.y = ay; o.z = az; o.w = aw;
    reinterpret_cast<float4*>(g_part)[idx] = o;
}

// ---------------------------------------------------------------------------
// Pass 2: exact k-th-largest per batch via 3-pass MSB radix select
// (11/11/10 bits). Pass 0 fuses the partial-energy combine (reads 3 partials
// from L2, writes combined e2, histograms high bits in one sweep).
// Parallel suffix-scan bin pick; fused maskbit build at the end.
// energy2 >= 0 so uint bit order == float order.
// ---------------------------------------------------------------------------
__global__ void select_kernel() {
    int b   = blockIdx.x;
    int tid = threadIdx.x;
    float4*       e2_4  = reinterpret_cast<float4*>(g_e2) + b * HW4;
    const float4* part  = reinterpret_cast<const float4*>(g_part) + b * HW4;
    const unsigned int* keys  = reinterpret_cast<const unsigned int*>(g_e2) + b * HW;
    const uint4*        keys4 = reinterpret_cast<const uint4*>(keys);

    __shared__ unsigned int hist[NB];
    __shared__ unsigned int ss[1024];
    __shared__ unsigned int s_prefix;
    __shared__ unsigned int s_remk;

    unsigned int prefix = 0;
    unsigned int remk   = KSEL;

#pragma unroll
    for (int pass = 0; pass < 3; pass++) {
        const int shift = (pass == 0) ? 21 : (pass == 1) ? 10 : 0;
        const unsigned int pmask =
            (pass == 0) ? 0u : (pass == 1) ? 0xFFE00000u : 0xFFFFFC00u;

        for (int i = tid; i < NB; i += 1024) hist[i] = 0;
        __syncthreads();

        if (pass == 0) {
            // Fused combine + histogram of bits [31:21].
            for (int i = tid; i < HW4; i += 1024) {
                float4 a = part[i];
                float4 p1 = part[i + B * HW4];
                float4 p2 = part[i + 2 * B * HW4];
                float4 e;
                e.x = a.x + p1.x + p2.x;
                e.y = a.y + p1.y + p2.y;
                e.z = a.z + p1.z + p2.z;
                e.w = a.w + p1.w + p2.w;
                e2_4[i] = e;
#pragma unroll
                for (int j = 0; j < 4; j++) {
                    float f = (j == 0) ? e.x : (j == 1) ? e.y : (j == 2) ? e.z : e.w;
                    unsigned int dig = __float_as_uint(f) >> 21;
                    unsigned int m = __match_any_sync(0xFFFFFFFFu, dig);
                    if ((int)(tid & 31) == (__ffs(m) - 1))
                        atomicAdd(&hist[dig], (unsigned)__popc(m));
                }
            }
        } else {
            for (int i = tid; i < HW4; i += 1024) {
                uint4 kv = keys4[i];
#pragma unroll
                for (int j = 0; j < 4; j++) {
                    unsigned int key = (j == 0) ? kv.x : (j == 1) ? kv.y : (j == 2) ? kv.z : kv.w;
                    unsigned int dig = ((key & pmask) == prefix)
                                           ? ((key >> shift) & 2047u)
                                           : 0xFFFFFFFFu;
                    unsigned int m = __match_any_sync(0xFFFFFFFFu, dig);
                    if (dig != 0xFFFFFFFFu && (int)(tid & 31) == (__ffs(m) - 1))
                        atomicAdd(&hist[dig], (unsigned)__popc(m));
                }
            }
        }
        __syncthreads();

        // Parallel suffix sums over 1024 two-bin segments (Hillis-Steele).
        unsigned int h0 = hist[2 * tid], h1 = hist[2 * tid + 1];
        ss[tid] = h0 + h1;
        __syncthreads();
        for (int off = 1; off < 1024; off <<= 1) {
            unsigned int v = (tid + off < 1024) ? ss[tid + off] : 0u;
            __syncthreads();
            ss[tid] += v;
            __syncthreads();
        }
        unsigned int ss_next = (tid + 1 < 1024) ? ss[tid + 1] : 0u;
        // S(2t+1) = ss_next + h1 ; S(2t) = S(2t+1) + h0 ; S(2t+2) = ss_next.
        unsigned int S1 = ss_next + h1;
        unsigned int S0 = S1 + h0;
        unsigned int S2 = ss_next;
        // Exactly one bin satisfies S(bin) >= remk && S(bin+1) < remk.
        if (S1 >= remk && S2 < remk) {
            s_prefix = prefix | ((2u * tid + 1u) << shift);
            s_remk   = remk - S2;
        }
        if (S0 >= remk && S1 < remk) {
            s_prefix = prefix | ((2u * tid) << shift);
            s_remk   = remk - S1;
        }
        __syncthreads();
        prefix = s_prefix;
        remk   = s_remk;
        __syncthreads();   // protect hist reuse next pass
    }

    // Fused maskbuild: ballot-pack (key >= thresh). 49 exact iterations.
    unsigned int t = prefix;
    for (int i = tid; i < HW; i += 1024) {
        unsigned int key = keys[i];
        unsigned int bal = __ballot_sync(0xFFFFFFFFu, key >= t);
        if ((tid & 31) == 0) g_maskbits[(b * HW + i) >> 5] = bal;
    }
}

// ---------------------------------------------------------------------------
// Pass 3: out = x * mask. 2 float4 per thread (one maskbits word serves both),
// streaming loads/stores to keep L2 clean. At HBM roofline.
// ---------------------------------------------------------------------------
__global__ void mask_kernel(const float4* __restrict__ x, float4* __restrict__ out) {
    int t = blockIdx.x * blockDim.x + threadIdx.x;        // over B*C*HW4/2
    if (t >= B * C * HW4 / 2) return;
    int idx = t * 2;
    int b  = idx / (C * HW4);
    int p  = idx % HW4;
    int hw = p * 4;
    unsigned int bits = g_maskbits[((unsigned)(b * HW + hw)) >> 5] >> (hw & 31);
    float4 v0 = __ldcs(x + (size_t)idx);
    float4 v1 = __ldcs(x + (size_t)idx + 1);
    float4 r0, r1;
    r0.x = (bits &   1u) ? v0.x : 0.f;
    r0.y = (bits &   2u) ? v0.y : 0.f;
    r0.z = (bits &   4u) ? v0.z : 0.f;
    r0.w = (bits &   8u) ? v0.w : 0.f;
    r1.x = (bits &  16u) ? v1.x : 0.f;
    r1.y = (bits &  32u) ? v1.y : 0.f;
    r1.z = (bits &  64u) ? v1.z : 0.f;
    r1.w = (bits & 128u) ? v1.w : 0.f;
    __stcs(out + (size_t)idx,     r0);
    __stcs(out + (size_t)idx + 1, r1);
}

extern "C" void kernel_launch(void* const* d_in, const int* in_sizes, int n_in,
                              void* d_out, int out_size) {
    const float* x = (const float*)d_in[0];
    float*     out = (float*)d_out;

    energy_kernel<<<(CHUNKS * B * HW4) / 256, 256>>>((const float4*)x);
    select_kernel<<<B, 1024>>>();
    mask_kernel<<<(B * C * HW4 / 2 + 255) / 256, 256>>>((const float4*)x, (float4*)out);
}